// round 11
// baseline (speedup 1.0000x reference)
#include <cuda_runtime.h>
#include <cuda_fp16.h>
#include <cstdint>

#define BB 8
#define CC 512
#define LL 2048

// ---------------------------------------------------------------------------
// Device scratch (all fp16 operands)
// ---------------------------------------------------------------------------
__device__ __half g_xt16[(size_t)BB * LL * CC];    // x^T [b][l][c]
__device__ __half g_w16[3 * CC * CC];              // W   [w][c_out][c_in]
__device__ __half g_qt16[(size_t)BB * LL * CC];    // q^T [b][l][c]
__device__ __half g_kt16[(size_t)BB * LL * CC];    // k^T [b][m][c]
__device__ __half g_v16[(size_t)BB * CC * LL];     // v   [b][c][m]
__device__ __half g_e16[(size_t)BB * LL * LL];     // e^s [b][l][m]
__device__ float  g_psum[(size_t)BB * LL * 16];    // partial row sums

// ---------------------------------------------------------------------------
// Helpers (baseline PTX only)
// ---------------------------------------------------------------------------
__device__ __forceinline__ uint32_t smem_u32(const void* p) {
    uint32_t a;
    asm("{ .reg .u64 t; cvta.to.shared.u64 t, %1; cvt.u32.u64 %0, t; }"
        : "=r"(a) : "l"(p));
    return a;
}

__device__ __forceinline__ void ldsm4(uint32_t* r, uint32_t addr) {
    asm volatile("ldmatrix.sync.aligned.m8n8.x4.shared.b16 {%0,%1,%2,%3}, [%4];"
                 : "=r"(r[0]), "=r"(r[1]), "=r"(r[2]), "=r"(r[3]) : "r"(addr));
}

__device__ __forceinline__ void mma16816h(float* c, const uint32_t* a, const uint32_t* b) {
    asm volatile(
        "mma.sync.aligned.m16n8k16.row.col.f32.f16.f16.f32 "
        "{%0,%1,%2,%3}, {%4,%5,%6,%7}, {%8,%9}, {%0,%1,%2,%3};"
        : "+f"(c[0]), "+f"(c[1]), "+f"(c[2]), "+f"(c[3])
        : "r"(a[0]), "r"(a[1]), "r"(a[2]), "r"(a[3]), "r"(b[0]), "r"(b[1]));
}

#define CP16(dst, src) \
    asm volatile("cp.async.cg.shared.global [%0], [%1], 16;" :: "r"(dst), "l"(src))
#define CP_COMMIT() asm volatile("cp.async.commit_group;" ::: "memory")
#define CP_WAIT0()  asm volatile("cp.async.wait_group 0;" ::: "memory")

// ---------------------------------------------------------------------------
// Fused conversion kernel: z<BB -> x transpose+convert for batch z;
// z==BB -> W convert.
// ---------------------------------------------------------------------------
__global__ __launch_bounds__(256) void conv_fused(
    const float* __restrict__ x,
    const float* __restrict__ Wq, const float* __restrict__ Wk,
    const float* __restrict__ Wv)
{
    int z = blockIdx.z;
    if (z < BB) {
        __shared__ float ts[32][33];
        int b = z, c0 = blockIdx.y * 32, l0 = blockIdx.x * 32;
        int lane = threadIdx.x & 31, wrp = threadIdx.x >> 5;
        const float* X = x + ((size_t)b * CC + c0) * LL + l0;
        #pragma unroll
        for (int ii = 0; ii < 4; ii++)
            ts[wrp + 8 * ii][lane] = X[(size_t)(wrp + 8 * ii) * LL + lane];
        __syncthreads();
        size_t base = ((size_t)b * LL + l0) * CC + c0;
        #pragma unroll
        for (int ii = 0; ii < 4; ii++) {
            int lr = wrp + 8 * ii;
            g_xt16[base + (size_t)lr * CC + lane] = __float2half(ts[lane][lr]);
        }
    } else {
        int t = (blockIdx.y * 64 + blockIdx.x) * 256 + threadIdx.x;
        g_w16[t]          = __float2half(Wq[t]);
        g_w16[t + 262144] = __float2half(Wk[t]);
        g_w16[t + 524288] = __float2half(Wv[t]);
    }
}

// ---------------------------------------------------------------------------
// Common tile copier (128 threads): 128 rows x 32 fp16 (64B), 80B pitch
// ---------------------------------------------------------------------------
__device__ __forceinline__ void cp_tile(uint32_t dst_base,
    const __half* __restrict__ g, int row0, int ld, int k0, int tid)
{
    #pragma unroll
    for (int i = 0; i < 4; i++) {
        int idx = i * 128 + tid;
        int r = idx >> 2, u = idx & 3;
        uint32_t dst = dst_base + (uint32_t)r * 80u + (uint32_t)u * 16u;
        const __half* src = g + (size_t)(row0 + r) * ld + k0 + u * 8;
        CP16(dst, src);
    }
}

// 64x64 warp tile: 4 m-subtiles x 8 n-subtiles, acc[128]
__device__ __forceinline__ void mma_block_h(float* acc, const uint32_t* af, const uint32_t* bf)
{
    #pragma unroll
    for (int i = 0; i < 4; i++)
        #pragma unroll
        for (int j = 0; j < 8; j++)
            mma16816h(acc + (i * 8 + j) * 4, af + i * 4, bf + (j >> 1) * 4 + (j & 1) * 2);
}

// ---------------------------------------------------------------------------
// GEMM mainloop: CTA 128x128, 4 warps of 64x64, BK=64 per stage, 2-stage
// double buffer (one wait+sync per 64-k) + register fragment double buffer.
// Stage layout: A0@0  A1@10240  B0@20480  B1@30720 ; stage stride 40960.
// ---------------------------------------------------------------------------
#define STG 40960
#define STAGE_BYTES (2 * STG)
#define SMEM_DYN  (STAGE_BYTES + 512)    // + rinv[128] for out_kernel

// fragments for k16 phase p (0..3): chunk p>>1, k-half (p&1)*32 bytes
__device__ __forceinline__ void ld_frags_p(uint32_t base, uint32_t aoff, uint32_t boff,
                                           int p, uint32_t* af, uint32_t* bf)
{
    uint32_t off = (uint32_t)(p >> 1) * 10240u + (uint32_t)(p & 1) * 32u;
    #pragma unroll
    for (int i = 0; i < 4; i++)  ldsm4(af + i * 4, base + off + aoff + i * 1280);
    #pragma unroll
    for (int jp = 0; jp < 4; jp++) ldsm4(bf + jp * 4, base + 20480 + off + boff + jp * 1280);
}

__device__ __forceinline__ void gemm_prologue(
    uint32_t sb, const __half* A, const __half* B, int m0, int n0,
    int lda, int ldb, int tid)
{
    cp_tile(sb + 0,     A, m0, lda, 0, tid);
    cp_tile(sb + 10240, A, m0, lda, 32, tid);
    cp_tile(sb + 20480, B, n0, ldb, 0, tid);
    cp_tile(sb + 30720, B, n0, ldb, 32, tid);
    CP_COMMIT();
}

__device__ __forceinline__ void gemm_mainloop(
    uint32_t sb, const __half* A, const __half* B, int m0, int n0,
    int lda, int ldb, int NT2, int tid, uint32_t aoff, uint32_t boff, float* acc)
{
    uint32_t af[2][16], bf[2][16];

    for (int t = 0; t < NT2; t++) {
        CP_WAIT0();
        __syncthreads();
        const uint32_t base = sb + (uint32_t)(t & 1) * STG;
        if (t + 1 < NT2) {
            uint32_t nb = sb + (uint32_t)((t + 1) & 1) * STG;
            int k0 = (t + 1) * 64;
            cp_tile(nb + 0,     A, m0, lda, k0, tid);
            cp_tile(nb + 10240, A, m0, lda, k0 + 32, tid);
            cp_tile(nb + 20480, B, n0, ldb, k0, tid);
            cp_tile(nb + 30720, B, n0, ldb, k0 + 32, tid);
            CP_COMMIT();
        }
        ld_frags_p(base, aoff, boff, 0, af[0], bf[0]);
        #pragma unroll
        for (int p = 0; p < 4; p++) {
            if (p < 3)
                ld_frags_p(base, aoff, boff, p + 1, af[(p + 1) & 1], bf[(p + 1) & 1]);
            mma_block_h(acc, af[p & 1], bf[p & 1]);
        }
    }
}

#define WARP_GEOM \
    const int tid = threadIdx.x; \
    const int lane = tid & 31, wid = tid >> 5; \
    const int wm = wid & 1, wn = wid >> 1; \
    const uint32_t aoff = (uint32_t)((wm * 64 + (lane & 15)) * 80 + ((lane >> 4) * 16)); \
    const uint32_t boff = (uint32_t)((wn * 64 + (((lane >> 3) >> 1) * 8) + (lane & 7)) * 80 \
                                     + ((lane >> 3) & 1) * 16);

// ---------------------------------------------------------------------------
// proj: fp16 GEMM. wsel<2: D[l][c_out]=x_t*W^T -> q/k ; wsel=2: D[c][l] -> v
// ---------------------------------------------------------------------------
__global__ __launch_bounds__(128, 2) void proj_kernel(
    const float* __restrict__ bq, const float* __restrict__ bk,
    const float* __restrict__ bv)
{
    extern __shared__ char smem[];
    const uint32_t sb = smem_u32(smem);
    WARP_GEOM

    int id = blockIdx.x;
    int b = blockIdx.y / 3, wsel = blockIdx.y % 3;
    const __half *A, *B;
    int m0, n0;
    if (wsel < 2) {
        m0 = (id >> 2) * 128; n0 = (id & 3) * 128;           // m=l, n=c_out
        A = g_xt16 + (size_t)b * LL * CC;
        B = g_w16 + (size_t)wsel * CC * CC;
    } else {
        m0 = (id & 3) * 128; n0 = (id >> 2) * 128;           // m=c_out, n=l
        A = g_w16 + (size_t)2 * CC * CC;
        B = g_xt16 + (size_t)b * LL * CC;
    }

    float acc[128];
    #pragma unroll
    for (int i = 0; i < 128; i++) acc[i] = 0.f;

    gemm_prologue(sb, A, B, m0, n0, CC, CC, tid);
    gemm_mainloop(sb, A, B, m0, n0, CC, CC, CC / 64, tid, aoff, boff, acc);

    const int mb = m0 + wm * 64;
    const int nb = n0 + wn * 64;

    if (wsel < 2) {
        const float* bias = (wsel == 0) ? bq : bk;
        __half* Q = ((wsel == 0) ? g_qt16 : g_kt16) + (size_t)b * LL * CC;
        #pragma unroll
        for (int i = 0; i < 4; i++) {
            int r0 = mb + i * 16 + (lane >> 2);
            #pragma unroll
            for (int j = 0; j < 8; j++) {
                const float* c = acc + (i * 8 + j) * 4;
                int nn = nb + j * 8 + (lane & 3) * 2;
                float b0 = bias[nn], b1 = bias[nn + 1];
                *(__half2*)(Q + (size_t)r0 * CC + nn) =
                    __floats2half2_rn(c[0] + b0, c[1] + b1);
                *(__half2*)(Q + (size_t)(r0 + 8) * CC + nn) =
                    __floats2half2_rn(c[2] + b0, c[3] + b1);
            }
        }
    } else {
        __half* V = g_v16 + (size_t)b * CC * LL;
        #pragma unroll
        for (int i = 0; i < 4; i++) {
            int r0 = mb + i * 16 + (lane >> 2);
            float bi0 = bv[r0], bi8 = bv[r0 + 8];
            #pragma unroll
            for (int j = 0; j < 8; j++) {
                const float* c = acc + (i * 8 + j) * 4;
                int nn = nb + j * 8 + (lane & 3) * 2;
                *(__half2*)(V + (size_t)r0 * LL + nn) =
                    __floats2half2_rn(c[0] + bi0, c[1] + bi0);
                *(__half2*)(V + (size_t)(r0 + 8) * LL + nn) =
                    __floats2half2_rn(c[2] + bi8, c[3] + bi8);
            }
        }
    }
}

// ---------------------------------------------------------------------------
// scores: D = q_t * k_t^T; emits e^(s*scale) fp16 + row partial sums
// ---------------------------------------------------------------------------
__global__ __launch_bounds__(128, 2) void scores_kernel()
{
    extern __shared__ char smem[];
    const uint32_t sb = smem_u32(smem);
    WARP_GEOM

    const int b = blockIdx.y;
    const int m0 = (blockIdx.x >> 4) * 128;    // l
    const int n0 = (blockIdx.x & 15) * 128;    // m
    const __half* Q = g_qt16 + (size_t)b * LL * CC;
    const __half* K = g_kt16 + (size_t)b * LL * CC;

    float acc[128];
    #pragma unroll
    for (int i = 0; i < 128; i++) acc[i] = 0.f;

    gemm_prologue(sb, Q, K, m0, n0, CC, CC, tid);
    gemm_mainloop(sb, Q, K, m0, n0, CC, CC, CC / 64, tid, aoff, boff, acc);

    const float scale = 0.044194173824159216f;   // 1/sqrt(512)
    const int mb = m0 + wm * 64;
    const int nb = n0 + wn * 64;
    __half* E = g_e16 + (size_t)b * LL * LL;

    __syncthreads();
    float* ps = (float*)smem;                     // [128][2]

    #pragma unroll
    for (int i = 0; i < 4; i++) {
        int r0 = mb + i * 16 + (lane >> 2);
        float sA = 0.f, sB = 0.f;
        #pragma unroll
        for (int j = 0; j < 8; j++) {
            const float* c = acc + (i * 8 + j) * 4;
            int nn = nb + j * 8 + (lane & 3) * 2;
            float e0 = __expf(fminf(c[0] * scale, 11.f));
            float e1 = __expf(fminf(c[1] * scale, 11.f));
            float e2 = __expf(fminf(c[2] * scale, 11.f));
            float e3 = __expf(fminf(c[3] * scale, 11.f));
            *(__half2*)(E + (size_t)r0 * LL + nn)       = __floats2half2_rn(e0, e1);
            *(__half2*)(E + (size_t)(r0 + 8) * LL + nn) = __floats2half2_rn(e2, e3);
            sA += e0 + e1;
            sB += e2 + e3;
        }
        #pragma unroll
        for (int o = 1; o <= 2; o <<= 1) {
            sA += __shfl_xor_sync(0xFFFFFFFFu, sA, o);
            sB += __shfl_xor_sync(0xFFFFFFFFu, sB, o);
        }
        if ((lane & 3) == 0) {
            int rloc = wm * 64 + i * 16 + (lane >> 2);
            ps[rloc * 2 + wn]       = sA;
            ps[(rloc + 8) * 2 + wn] = sB;
        }
    }
    __syncthreads();
    {
        float s = ps[tid * 2] + ps[tid * 2 + 1];
        g_psum[((size_t)b * LL + m0 + tid) * 16 + (n0 >> 7)] = s;
    }
}

// ---------------------------------------------------------------------------
// out = (V * E^T) * rinv.  rinv computed in-CTA from g_psum.
// ---------------------------------------------------------------------------
__global__ __launch_bounds__(128, 2) void out_kernel(float* __restrict__ outp)
{
    extern __shared__ char smem[];
    const uint32_t sb = smem_u32(smem);
    WARP_GEOM

    const int b = blockIdx.y;
    const int m0 = (blockIdx.x & 3) * 128;     // c
    const int n0 = (blockIdx.x >> 2) * 128;    // l
    const __half* V = g_v16 + (size_t)b * CC * LL;
    const __half* E = g_e16 + (size_t)b * LL * LL;

    float acc[128];
    #pragma unroll
    for (int i = 0; i < 128; i++) acc[i] = 0.f;

    gemm_prologue(sb, V, E, m0, n0, LL, LL, tid);

    // rinv for this CTA's 128 l-rows, overlapped with the cp.async prologue.
    // Visible to all threads via the mainloop's internal __syncthreads.
    float* srinv = (float*)(smem + STAGE_BYTES);
    {
        const float* p = &g_psum[((size_t)b * LL + n0 + tid) * 16];
        float s = 0.f;
        #pragma unroll
        for (int k = 0; k < 16; k++) s += p[k];
        srinv[tid] = 1.f / s;
    }

    gemm_mainloop(sb, V, E, m0, n0, LL, LL, LL / 64, tid, aoff, boff, acc);

    const int mb = m0 + wm * 64;
    const int nb = n0 + wn * 64;
    float rv[16];
    #pragma unroll
    for (int j = 0; j < 8; j++) {
        int nn = (nb - n0) + j * 8 + (lane & 3) * 2;
        float2 r2 = *(const float2*)&srinv[nn];
        rv[j * 2] = r2.x; rv[j * 2 + 1] = r2.y;
    }

    float* O = outp + (size_t)b * CC * LL;
    #pragma unroll
    for (int i = 0; i < 4; i++) {
        int r0 = mb + i * 16 + (lane >> 2);
        #pragma unroll
        for (int j = 0; j < 8; j++) {
            const float* c = acc + (i * 8 + j) * 4;
            int nn = nb + j * 8 + (lane & 3) * 2;
            float2 v0 = {c[0] * rv[j * 2], c[1] * rv[j * 2 + 1]};
            float2 v1 = {c[2] * rv[j * 2], c[3] * rv[j * 2 + 1]};
            *(float2*)&O[(size_t)r0 * LL + nn]       = v0;
            *(float2*)&O[(size_t)(r0 + 8) * LL + nn] = v1;
        }
    }
}

// ---------------------------------------------------------------------------
extern "C" void kernel_launch(void* const* d_in, const int* in_sizes, int n_in,
                              void* d_out, int out_size)
{
    const float* x  = (const float*)d_in[0];
    const float* Wq = (const float*)d_in[1];
    const float* bq = (const float*)d_in[2];
    const float* Wk = (const float*)d_in[3];
    const float* bk = (const float*)d_in[4];
    const float* Wv = (const float*)d_in[5];
    const float* bv = (const float*)d_in[6];
    float* out = (float*)d_out;

    cudaFuncSetAttribute(proj_kernel,   cudaFuncAttributeMaxDynamicSharedMemorySize, SMEM_DYN);
    cudaFuncSetAttribute(scores_kernel, cudaFuncAttributeMaxDynamicSharedMemorySize, SMEM_DYN);
    cudaFuncSetAttribute(out_kernel,    cudaFuncAttributeMaxDynamicSharedMemorySize, SMEM_DYN);

    conv_fused<<<dim3(LL / 32, CC / 32, BB + 1), 256>>>(x, Wq, Wk, Wv);

    proj_kernel<<<dim3(64, 3 * BB), 128, SMEM_DYN>>>(bq, bk, bv);
    scores_kernel<<<dim3(256, BB), 128, SMEM_DYN>>>();
    out_kernel<<<dim3(64, BB), 128, SMEM_DYN>>>(out);
}

// round 12
// speedup vs baseline: 1.2223x; 1.2223x over previous
#include <cuda_runtime.h>
#include <cuda_fp16.h>
#include <cstdint>

#define BB 8
#define CC 512
#define LL 2048

// ---------------------------------------------------------------------------
// Device scratch (all fp16 operands)
// ---------------------------------------------------------------------------
__device__ __half g_xt16[(size_t)BB * LL * CC];    // x^T [b][l][c]
__device__ __half g_w16[3 * CC * CC];              // W   [w][c_out][c_in]
__device__ __half g_qt16[(size_t)BB * LL * CC];    // q^T [b][l][c]
__device__ __half g_kt16[(size_t)BB * LL * CC];    // k^T [b][m][c]
__device__ __half g_v16[(size_t)BB * CC * LL];     // v   [b][c][m]
__device__ __half g_e16[(size_t)BB * LL * LL];     // e^s [b][l][m]
__device__ float  g_psum[(size_t)BB * LL * 16];    // partial row sums

// ---------------------------------------------------------------------------
// Helpers (baseline PTX only)
// ---------------------------------------------------------------------------
__device__ __forceinline__ uint32_t smem_u32(const void* p) {
    uint32_t a;
    asm("{ .reg .u64 t; cvta.to.shared.u64 t, %1; cvt.u32.u64 %0, t; }"
        : "=r"(a) : "l"(p));
    return a;
}

__device__ __forceinline__ void ldsm4(uint32_t* r, uint32_t addr) {
    asm volatile("ldmatrix.sync.aligned.m8n8.x4.shared.b16 {%0,%1,%2,%3}, [%4];"
                 : "=r"(r[0]), "=r"(r[1]), "=r"(r[2]), "=r"(r[3]) : "r"(addr));
}

__device__ __forceinline__ void mma16816h(float* c, const uint32_t* a, const uint32_t* b) {
    asm volatile(
        "mma.sync.aligned.m16n8k16.row.col.f32.f16.f16.f32 "
        "{%0,%1,%2,%3}, {%4,%5,%6,%7}, {%8,%9}, {%0,%1,%2,%3};"
        : "+f"(c[0]), "+f"(c[1]), "+f"(c[2]), "+f"(c[3])
        : "r"(a[0]), "r"(a[1]), "r"(a[2]), "r"(a[3]), "r"(b[0]), "r"(b[1]));
}

#define CP16(dst, src) \
    asm volatile("cp.async.cg.shared.global [%0], [%1], 16;" :: "r"(dst), "l"(src))
#define CP_COMMIT() asm volatile("cp.async.commit_group;" ::: "memory")
#define CP_WAIT2()  asm volatile("cp.async.wait_group 2;" ::: "memory")

// ---------------------------------------------------------------------------
// Fused conversion kernel: z<BB -> x transpose+convert for batch z;
// z==BB -> W convert.
// ---------------------------------------------------------------------------
__global__ __launch_bounds__(256) void conv_fused(
    const float* __restrict__ x,
    const float* __restrict__ Wq, const float* __restrict__ Wk,
    const float* __restrict__ Wv)
{
    int z = blockIdx.z;
    if (z < BB) {
        __shared__ float ts[32][33];
        int b = z, c0 = blockIdx.y * 32, l0 = blockIdx.x * 32;
        int lane = threadIdx.x & 31, wrp = threadIdx.x >> 5;
        const float* X = x + ((size_t)b * CC + c0) * LL + l0;
        #pragma unroll
        for (int ii = 0; ii < 4; ii++)
            ts[wrp + 8 * ii][lane] = X[(size_t)(wrp + 8 * ii) * LL + lane];
        __syncthreads();
        size_t base = ((size_t)b * LL + l0) * CC + c0;
        #pragma unroll
        for (int ii = 0; ii < 4; ii++) {
            int lr = wrp + 8 * ii;
            g_xt16[base + (size_t)lr * CC + lane] = __float2half(ts[lane][lr]);
        }
    } else {
        int t = (blockIdx.y * 64 + blockIdx.x) * 256 + threadIdx.x;
        g_w16[t]          = __float2half(Wq[t]);
        g_w16[t + 262144] = __float2half(Wk[t]);
        g_w16[t + 524288] = __float2half(Wv[t]);
    }
}

// ---------------------------------------------------------------------------
// Common tile copier (128 threads): 128 rows x 32 fp16 (64B), 80B pitch
// ---------------------------------------------------------------------------
__device__ __forceinline__ void cp_tile(uint32_t dst_base,
    const __half* __restrict__ g, int row0, int ld, int k0, int tid)
{
    #pragma unroll
    for (int i = 0; i < 4; i++) {
        int idx = i * 128 + tid;
        int r = idx >> 2, u = idx & 3;
        uint32_t dst = dst_base + (uint32_t)r * 80u + (uint32_t)u * 16u;
        const __half* src = g + (size_t)(row0 + r) * ld + k0 + u * 8;
        CP16(dst, src);
    }
}

// 64x64 warp tile: 4 m-subtiles x 8 n-subtiles, acc[128]
__device__ __forceinline__ void mma_block_h(float* acc, const uint32_t* af, const uint32_t* bf)
{
    #pragma unroll
    for (int i = 0; i < 4; i++)
        #pragma unroll
        for (int j = 0; j < 8; j++)
            mma16816h(acc + (i * 8 + j) * 4, af + i * 4, bf + (j >> 1) * 4 + (j & 1) * 2);
}

// ---------------------------------------------------------------------------
// Shared GEMM mainloop: CTA 128x128, 4 warps of 64x64, BK=32, 4-stage
// cp.async pipeline (wait_group 2: copy committed ~2 iters before its wait)
// + register fragment double-buffering.
// Stage: A@0, B@10240; stage stride 20480; stages total 81920.
// ---------------------------------------------------------------------------
#define STG 20480
#define NSTAGE 4
#define STAGE_BYTES (NSTAGE * STG)
#define SMEM_DYN  (STAGE_BYTES + 512)    // + rinv[128] for out_kernel

__device__ __forceinline__ void ld_frags(uint32_t base, uint32_t aoff, uint32_t boff,
                                         uint32_t kb, uint32_t* af, uint32_t* bf)
{
    #pragma unroll
    for (int i = 0; i < 4; i++)  ldsm4(af + i * 4, base + aoff + i * 1280 + kb);
    #pragma unroll
    for (int jp = 0; jp < 4; jp++) ldsm4(bf + jp * 4, base + 10240 + boff + jp * 1280 + kb);
}

// prologue: stages 0..2 in flight (3 commit groups)
__device__ __forceinline__ void gemm_prologue(
    uint32_t sb, const __half* A, const __half* B, int m0, int n0,
    int lda, int ldb, int tid)
{
    #pragma unroll
    for (int s = 0; s < 3; s++) {
        uint32_t st = sb + (uint32_t)s * STG;
        cp_tile(st + 0,     A, m0, lda, s * 32, tid);
        cp_tile(st + 10240, B, n0, ldb, s * 32, tid);
        CP_COMMIT();
    }
}

__device__ __forceinline__ void gemm_mainloop(
    uint32_t sb, const __half* A, const __half* B, int m0, int n0,
    int lda, int ldb, int NT, int tid, uint32_t aoff, uint32_t boff, float* acc)
{
    CP_WAIT2();                 // stage 0 resident (2 groups may stay in flight)
    __syncthreads();

    uint32_t af[2][16], bf[2][16];
    ld_frags(sb, aoff, boff, 0, af[0], bf[0]);

    for (int t = 0; t < NT; t++) {
        const uint32_t base = sb + (uint32_t)(t & (NSTAGE - 1)) * STG;
        if (t + 3 < NT) {
            uint32_t nb = sb + (uint32_t)((t + 3) & (NSTAGE - 1)) * STG;
            int k0 = (t + 3) * 32;
            cp_tile(nb + 0,     A, m0, lda, k0, tid);
            cp_tile(nb + 10240, B, n0, ldb, k0, tid);
        }
        CP_COMMIT();            // one group per iteration (possibly empty)

        // phase ks=0: prefetch ks=1 frags, MMA on ks=0
        ld_frags(base, aoff, boff, 32, af[1], bf[1]);
        mma_block_h(acc, af[0], bf[0]);

        // phase ks=1: wait next stage, prefetch next tile's ks=0, MMA ks=1
        if (t + 1 < NT) {
            CP_WAIT2();         // stage t+1 resident (committed 2 iters ago)
            __syncthreads();
            const uint32_t nbase = sb + (uint32_t)((t + 1) & (NSTAGE - 1)) * STG;
            ld_frags(nbase, aoff, boff, 0, af[0], bf[0]);
        }
        mma_block_h(acc, af[1], bf[1]);
    }
}

#define WARP_GEOM \
    const int tid = threadIdx.x; \
    const int lane = tid & 31, wid = tid >> 5; \
    const int wm = wid & 1, wn = wid >> 1; \
    const uint32_t aoff = (uint32_t)((wm * 64 + (lane & 15)) * 80 + ((lane >> 4) * 16)); \
    const uint32_t boff = (uint32_t)((wn * 64 + (((lane >> 3) >> 1) * 8) + (lane & 7)) * 80 \
                                     + ((lane >> 3) & 1) * 16);

// ---------------------------------------------------------------------------
// proj: fp16 GEMM. wsel<2: D[l][c_out]=x_t*W^T -> q/k ; wsel=2: D[c][l] -> v
// ---------------------------------------------------------------------------
__global__ __launch_bounds__(128, 2) void proj_kernel(
    const float* __restrict__ bq, const float* __restrict__ bk,
    const float* __restrict__ bv)
{
    extern __shared__ char smem[];
    const uint32_t sb = smem_u32(smem);
    WARP_GEOM

    int id = blockIdx.x;
    int b = blockIdx.y / 3, wsel = blockIdx.y % 3;
    const __half *A, *B;
    int m0, n0;
    if (wsel < 2) {
        m0 = (id >> 2) * 128; n0 = (id & 3) * 128;           // m=l, n=c_out
        A = g_xt16 + (size_t)b * LL * CC;
        B = g_w16 + (size_t)wsel * CC * CC;
    } else {
        m0 = (id & 3) * 128; n0 = (id >> 2) * 128;           // m=c_out, n=l
        A = g_w16 + (size_t)2 * CC * CC;
        B = g_xt16 + (size_t)b * LL * CC;
    }

    float acc[128];
    #pragma unroll
    for (int i = 0; i < 128; i++) acc[i] = 0.f;

    gemm_prologue(sb, A, B, m0, n0, CC, CC, tid);
    gemm_mainloop(sb, A, B, m0, n0, CC, CC, CC / 32, tid, aoff, boff, acc);

    const int mb = m0 + wm * 64;
    const int nb = n0 + wn * 64;

    if (wsel < 2) {
        const float* bias = (wsel == 0) ? bq : bk;
        __half* Q = ((wsel == 0) ? g_qt16 : g_kt16) + (size_t)b * LL * CC;
        #pragma unroll
        for (int i = 0; i < 4; i++) {
            int r0 = mb + i * 16 + (lane >> 2);
            #pragma unroll
            for (int j = 0; j < 8; j++) {
                const float* c = acc + (i * 8 + j) * 4;
                int nn = nb + j * 8 + (lane & 3) * 2;
                float b0 = bias[nn], b1 = bias[nn + 1];
                *(__half2*)(Q + (size_t)r0 * CC + nn) =
                    __floats2half2_rn(c[0] + b0, c[1] + b1);
                *(__half2*)(Q + (size_t)(r0 + 8) * CC + nn) =
                    __floats2half2_rn(c[2] + b0, c[3] + b1);
            }
        }
    } else {
        __half* V = g_v16 + (size_t)b * CC * LL;
        #pragma unroll
        for (int i = 0; i < 4; i++) {
            int r0 = mb + i * 16 + (lane >> 2);
            float bi0 = bv[r0], bi8 = bv[r0 + 8];
            #pragma unroll
            for (int j = 0; j < 8; j++) {
                const float* c = acc + (i * 8 + j) * 4;
                int nn = nb + j * 8 + (lane & 3) * 2;
                *(__half2*)(V + (size_t)r0 * LL + nn) =
                    __floats2half2_rn(c[0] + bi0, c[1] + bi0);
                *(__half2*)(V + (size_t)(r0 + 8) * LL + nn) =
                    __floats2half2_rn(c[2] + bi8, c[3] + bi8);
            }
        }
    }
}

// ---------------------------------------------------------------------------
// scores: D = q_t * k_t^T; emits e^(s*scale) fp16 + row partial sums
// ---------------------------------------------------------------------------
__global__ __launch_bounds__(128, 2) void scores_kernel()
{
    extern __shared__ char smem[];
    const uint32_t sb = smem_u32(smem);
    WARP_GEOM

    const int b = blockIdx.y;
    const int m0 = (blockIdx.x >> 4) * 128;    // l
    const int n0 = (blockIdx.x & 15) * 128;    // m
    const __half* Q = g_qt16 + (size_t)b * LL * CC;
    const __half* K = g_kt16 + (size_t)b * LL * CC;

    float acc[128];
    #pragma unroll
    for (int i = 0; i < 128; i++) acc[i] = 0.f;

    gemm_prologue(sb, Q, K, m0, n0, CC, CC, tid);
    gemm_mainloop(sb, Q, K, m0, n0, CC, CC, CC / 32, tid, aoff, boff, acc);

    const float scale = 0.044194173824159216f;   // 1/sqrt(512)
    const int mb = m0 + wm * 64;
    const int nb = n0 + wn * 64;
    __half* E = g_e16 + (size_t)b * LL * LL;

    __syncthreads();
    float* ps = (float*)smem;                     // [128][2]

    #pragma unroll
    for (int i = 0; i < 4; i++) {
        int r0 = mb + i * 16 + (lane >> 2);
        float sA = 0.f, sB = 0.f;
        #pragma unroll
        for (int j = 0; j < 8; j++) {
            const float* c = acc + (i * 8 + j) * 4;
            int nn = nb + j * 8 + (lane & 3) * 2;
            float e0 = __expf(fminf(c[0] * scale, 11.f));
            float e1 = __expf(fminf(c[1] * scale, 11.f));
            float e2 = __expf(fminf(c[2] * scale, 11.f));
            float e3 = __expf(fminf(c[3] * scale, 11.f));
            *(__half2*)(E + (size_t)r0 * LL + nn)       = __floats2half2_rn(e0, e1);
            *(__half2*)(E + (size_t)(r0 + 8) * LL + nn) = __floats2half2_rn(e2, e3);
            sA += e0 + e1;
            sB += e2 + e3;
        }
        #pragma unroll
        for (int o = 1; o <= 2; o <<= 1) {
            sA += __shfl_xor_sync(0xFFFFFFFFu, sA, o);
            sB += __shfl_xor_sync(0xFFFFFFFFu, sB, o);
        }
        if ((lane & 3) == 0) {
            int rloc = wm * 64 + i * 16 + (lane >> 2);
            ps[rloc * 2 + wn]       = sA;
            ps[(rloc + 8) * 2 + wn] = sB;
        }
    }
    __syncthreads();
    {
        float s = ps[tid * 2] + ps[tid * 2 + 1];
        g_psum[((size_t)b * LL + m0 + tid) * 16 + (n0 >> 7)] = s;
    }
}

// ---------------------------------------------------------------------------
// out = (V * E^T) * rinv.  rinv computed in-CTA from g_psum.
// ---------------------------------------------------------------------------
__global__ __launch_bounds__(128, 2) void out_kernel(float* __restrict__ outp)
{
    extern __shared__ char smem[];
    const uint32_t sb = smem_u32(smem);
    WARP_GEOM

    const int b = blockIdx.y;
    const int m0 = (blockIdx.x & 3) * 128;     // c
    const int n0 = (blockIdx.x >> 2) * 128;    // l
    const __half* V = g_v16 + (size_t)b * CC * LL;
    const __half* E = g_e16 + (size_t)b * LL * LL;

    float acc[128];
    #pragma unroll
    for (int i = 0; i < 128; i++) acc[i] = 0.f;

    gemm_prologue(sb, V, E, m0, n0, LL, LL, tid);

    // rinv for this CTA's 128 l-rows, overlapped with the cp.async prologue.
    // Visible to all threads via the mainloop's first __syncthreads.
    float* srinv = (float*)(smem + STAGE_BYTES);
    {
        const float* p = &g_psum[((size_t)b * LL + n0 + tid) * 16];
        float s = 0.f;
        #pragma unroll
        for (int k = 0; k < 16; k++) s += p[k];
        srinv[tid] = 1.f / s;
    }

    gemm_mainloop(sb, V, E, m0, n0, LL, LL, LL / 32, tid, aoff, boff, acc);

    const int mb = m0 + wm * 64;
    const int nb = n0 + wn * 64;
    float rv[16];
    #pragma unroll
    for (int j = 0; j < 8; j++) {
        int nn = (nb - n0) + j * 8 + (lane & 3) * 2;
        float2 r2 = *(const float2*)&srinv[nn];
        rv[j * 2] = r2.x; rv[j * 2 + 1] = r2.y;
    }

    float* O = outp + (size_t)b * CC * LL;
    #pragma unroll
    for (int i = 0; i < 4; i++) {
        int r0 = mb + i * 16 + (lane >> 2);
        #pragma unroll
        for (int j = 0; j < 8; j++) {
            const float* c = acc + (i * 8 + j) * 4;
            int nn = nb + j * 8 + (lane & 3) * 2;
            float2 v0 = {c[0] * rv[j * 2], c[1] * rv[j * 2 + 1]};
            float2 v1 = {c[2] * rv[j * 2], c[3] * rv[j * 2 + 1]};
            *(float2*)&O[(size_t)r0 * LL + nn]       = v0;
            *(float2*)&O[(size_t)(r0 + 8) * LL + nn] = v1;
        }
    }
}

// ---------------------------------------------------------------------------
extern "C" void kernel_launch(void* const* d_in, const int* in_sizes, int n_in,
                              void* d_out, int out_size)
{
    const float* x  = (const float*)d_in[0];
    const float* Wq = (const float*)d_in[1];
    const float* bq = (const float*)d_in[2];
    const float* Wk = (const float*)d_in[3];
    const float* bk = (const float*)d_in[4];
    const float* Wv = (const float*)d_in[5];
    const float* bv = (const float*)d_in[6];
    float* out = (float*)d_out;

    cudaFuncSetAttribute(proj_kernel,   cudaFuncAttributeMaxDynamicSharedMemorySize, SMEM_DYN);
    cudaFuncSetAttribute(scores_kernel, cudaFuncAttributeMaxDynamicSharedMemorySize, SMEM_DYN);
    cudaFuncSetAttribute(out_kernel,    cudaFuncAttributeMaxDynamicSharedMemorySize, SMEM_DYN);

    conv_fused<<<dim3(LL / 32, CC / 32, BB + 1), 256>>>(x, Wq, Wk, Wv);

    proj_kernel<<<dim3(64, 3 * BB), 128, SMEM_DYN>>>(bq, bk, bv);
    scores_kernel<<<dim3(256, BB), 128, SMEM_DYN>>>();
    out_kernel<<<dim3(64, BB), 128, SMEM_DYN>>>(out);
}